// round 2
// baseline (speedup 1.0000x reference)
#include <cuda_runtime.h>
#include <cstdint>

typedef unsigned long long u64;

#define HW 65536           // 256*256
#define NB 8
#define NC 32
#define NBC 256

// pooled x per (b,i) and final 5x5 filters per (b,o)
__device__ float g_px[NBC * 25];
__device__ float g_filt[NBC * 25];

__device__ __forceinline__ u64 fma2(u64 a, u64 b, u64 c) {
    u64 d;
    asm("fma.rn.f32x2 %0, %1, %2, %3;" : "=l"(d) : "l"(a), "l"(b), "l"(c));
    return d;
}
__device__ __forceinline__ u64 dup(float f) {
    unsigned u = __float_as_uint(f);
    return ((u64)u << 32) | (u64)u;
}

// ---------------------------------------------------------------------------
// Kernel 1: adaptive avg pool 256x256 -> 5x5 directly on x (per (b,i)).
// Bins: [0,52) [51,103) [102,154) [153,205) [204,256), all width 52.
// grid = 256 (b*32+i), block = 256
// ---------------------------------------------------------------------------
__global__ __launch_bounds__(256) void pool_kernel(const float* __restrict__ x)
{
    __shared__ float pool[25];
    int bc = blockIdx.x;
    int w = threadIdx.x;
    if (w < 25) pool[w] = 0.0f;
    __syncthreads();

    const float* img = x + (size_t)bc * HW;

    float cs0 = 0.f, cs1 = 0.f, cs2 = 0.f, cs3 = 0.f, cs4 = 0.f;
#pragma unroll
    for (int h = 0; h < 256; h++) {
        float v = img[h * 256 + w];
        if (h < 52)              cs0 += v;
        if (h >= 51 && h < 103)  cs1 += v;
        if (h >= 102 && h < 154) cs2 += v;
        if (h >= 153 && h < 205) cs3 += v;
        if (h >= 204)            cs4 += v;
    }
    float cs[5] = {cs0, cs1, cs2, cs3, cs4};

#pragma unroll
    for (int l = 0; l < 5; l++) {
        int s = (l * 256) / 5;
        int e = ((l + 1) * 256 + 4) / 5;
        if (w >= s && w < e) {
#pragma unroll
            for (int k = 0; k < 5; k++)
                atomicAdd(&pool[k * 5 + l], cs[k]);
        }
    }
    __syncthreads();
    if (w < 25)
        g_px[bc * 25 + w] = pool[w] * (1.0f / 2704.0f);   // 52*52
}

// ---------------------------------------------------------------------------
// Kernel 2: filt[b,o,kl] = bias[o] + sum_i w[o,i] * px[b,i,kl]
// (pooling commutes with the 1x1 conv since the pool matrix is row-stochastic)
// grid = 8 (batch), block = 800 (= 32 o * 25 kl, 25 warps)
// ---------------------------------------------------------------------------
__global__ void filt_kernel(const float* __restrict__ w,
                            const float* __restrict__ bias)
{
    __shared__ float spx[800];
    int b = blockIdx.x;
    int t = threadIdx.x;
    spx[t] = g_px[b * 800 + t];
    __syncthreads();

    int o = t / 25;
    int kl = t - o * 25;
    float acc = bias[o];
#pragma unroll
    for (int i = 0; i < 32; i++)
        acc += w[o * 32 + i] * spx[i * 25 + kl];
    g_filt[b * 800 + t] = acc;
}

// ---------------------------------------------------------------------------
// Kernel 3: fused channel-mix + depthwise 5x5 conv.
// Block = one (batch, 32x16 spatial tile), covering ALL 32 output channels.
// Stages x halo (32ch x 20 x 36) in SMEM once, then per output-channel pair:
//   mix: feat halo tile via packed f32x2 FMAs (x pairs + duplicated weights
//        broadcast from SMEM), masked to zero outside the image (conv padding)
//   conv: 5x5 cross-correlation from the feat SMEM tile, direct store to out.
// feat never touches DRAM.
// grid = (128, 8), block = 256, smem = 109568 B -> 2 blocks/SM (16 warps)
// ---------------------------------------------------------------------------
#define TH 16
#define HR 20              // halo rows
#define HC 36              // halo cols (== smem row stride)
#define CHS (HR * HC)      // 720 floats per channel
#define NPAIR (HR * 18)    // 360 float2 pairs per feat tile

__global__ __launch_bounds__(256, 2) void fused_kernel(
    const float* __restrict__ x,
    const float* __restrict__ w,
    const float* __restrict__ bias,
    float* __restrict__ out)
{
    extern __shared__ float smem[];
    float* xs  = smem;                  // [32][20][36]
    float* ft0 = xs + 32 * CHS;         // [20][36]
    float* ft1 = ft0 + CHS;             // [20][36]
    u64*   w2  = (u64*)(ft1 + CHS);     // [32][32] duplicated pairs
    u64*   b2  = w2 + 1024;             // [32]
    float* fs  = (float*)(b2 + 32);     // [32][25]

    int tid = threadIdx.x;
    int b   = blockIdx.y;
    int tx0 = (blockIdx.x & 7) * 32;
    int ty0 = (blockIdx.x >> 3) * TH;

    for (int idx = tid; idx < 1024; idx += 256)
        w2[idx] = dup(w[idx]);
    if (tid < 32)
        b2[tid] = dup(bias[tid]);
    for (int idx = tid; idx < 800; idx += 256)
        fs[idx] = g_filt[b * 800 + idx];

    // stage x halo tile for all 32 channels, zero-padded at image borders
    const float* xb = x + (size_t)b * (NC * HW);
    for (int e = tid; e < 32 * CHS; e += 256) {
        int i   = e / CHS;
        int rem = e - i * CHS;
        int r   = rem / HC;
        int col = rem - r * HC;
        int gy = ty0 + r - 2;
        int gx = tx0 + col - 2;
        float v = 0.0f;
        if ((unsigned)gy < 256u && (unsigned)gx < 256u)
            v = xb[i * HW + gy * 256 + gx];
        xs[e] = v;
    }

    // per-thread pair metadata (each thread owns up to 2 feat pixel-pairs)
    int  xoff[2];
    bool pval[2], pin[2];
#pragma unroll
    for (int p = 0; p < 2; p++) {
        int pi = tid + p * 256;
        pval[p] = pi < NPAIR;
        int r  = pi / 18;
        int pc = (pi - r * 18) * 2;
        xoff[p] = r * HC + pc;
        int gy = ty0 + r - 2;
        int gx = tx0 + pc - 2;
        pin[p] = ((unsigned)gy < 256u) && ((unsigned)gx < 256u);
    }
    __syncthreads();

    int ox = tid & 31;            // output column
    int oy = (tid >> 5) * 2;      // 2-high output rows
    float* outp = out + (size_t)b * NC * HW + (ty0 + oy) * 256 + tx0 + ox;

#pragma unroll 1
    for (int cg = 0; cg < 32; cg += 2) {
        // ---- mix: feat tiles for channels cg, cg+1 ----
        u64 a0[2], a1[2];
#pragma unroll
        for (int p = 0; p < 2; p++) { a0[p] = b2[cg]; a1[p] = b2[cg + 1]; }

#pragma unroll
        for (int ic = 0; ic < 32; ic += 8) {
            u64 wv0[8], wv1[8];
#pragma unroll
            for (int k = 0; k < 8; k++) {
                wv0[k] = w2[cg * 32 + ic + k];
                wv1[k] = w2[(cg + 1) * 32 + ic + k];
            }
#pragma unroll
            for (int p = 0; p < 2; p++) if (pval[p]) {
                const float* bp = xs + xoff[p] + ic * CHS;
#pragma unroll
                for (int k = 0; k < 8; k++) {
                    u64 xv = *(const u64*)(bp + k * CHS);
                    a0[p] = fma2(wv0[k], xv, a0[p]);
                    a1[p] = fma2(wv1[k], xv, a1[p]);
                }
            }
        }
#pragma unroll
        for (int p = 0; p < 2; p++) if (pval[p]) {
            *(u64*)(ft0 + xoff[p]) = pin[p] ? a0[p] : 0ull;
            *(u64*)(ft1 + xoff[p]) = pin[p] ? a1[p] : 0ull;
        }
        __syncthreads();

        // ---- conv: 5x5 cross-correlation for both channels ----
#pragma unroll
        for (int cc = 0; cc < 2; cc++) {
            const float* ftp = cc ? ft1 : ft0;
            const float* fp  = fs + (cg + cc) * 25;
            float f[25];
#pragma unroll
            for (int t = 0; t < 25; t++) f[t] = fp[t];

            float acc0 = 0.f, acc1 = 0.f;
#pragma unroll
            for (int r = 0; r < 6; r++) {
                float v0 = ftp[(oy + r) * HC + ox + 0];
                float v1 = ftp[(oy + r) * HC + ox + 1];
                float v2 = ftp[(oy + r) * HC + ox + 2];
                float v3 = ftp[(oy + r) * HC + ox + 3];
                float v4 = ftp[(oy + r) * HC + ox + 4];
#pragma unroll
                for (int ky = 0; ky < 5; ky++) {
                    if (r - ky == 0) {
                        acc0 += v0 * f[ky * 5 + 0];
                        acc0 += v1 * f[ky * 5 + 1];
                        acc0 += v2 * f[ky * 5 + 2];
                        acc0 += v3 * f[ky * 5 + 3];
                        acc0 += v4 * f[ky * 5 + 4];
                    }
                    if (r - ky == 1) {
                        acc1 += v0 * f[ky * 5 + 0];
                        acc1 += v1 * f[ky * 5 + 1];
                        acc1 += v2 * f[ky * 5 + 2];
                        acc1 += v3 * f[ky * 5 + 3];
                        acc1 += v4 * f[ky * 5 + 4];
                    }
                }
            }
            outp[(size_t)(cg + cc) * HW]       = acc0;
            outp[(size_t)(cg + cc) * HW + 256] = acc1;
        }
        __syncthreads();
    }
}

// ---------------------------------------------------------------------------
extern "C" void kernel_launch(void* const* d_in, const int* in_sizes, int n_in,
                              void* d_out, int out_size)
{
    const float* x    = (const float*)d_in[0];   // [8, 32, 256, 256]
    const float* w    = (const float*)d_in[1];   // [32, 32]
    const float* bias = (const float*)d_in[2];   // [32]
    float* out = (float*)d_out;                  // [8, 32, 256, 256]

    const int smem_bytes = (32 * CHS + 2 * CHS) * 4 + 1024 * 8 + 32 * 8 + 800 * 4;
    cudaFuncSetAttribute(fused_kernel,
                         cudaFuncAttributeMaxDynamicSharedMemorySize, smem_bytes);

    pool_kernel<<<NBC, 256>>>(x);
    filt_kernel<<<NB, 800>>>(w, bias);
    fused_kernel<<<dim3(128, NB), 256, smem_bytes>>>(x, w, bias, out);
}

// round 3
// speedup vs baseline: 1.0912x; 1.0912x over previous
#include <cuda_runtime.h>
#include <cstdint>

typedef unsigned long long u64;

#define HW 65536           // 256*256
#define NB 8
#define NC 32
#define NBC 256

// feat scratch, pooled-x partials (4 row-chunks), final 5x5 filters
__device__ float g_feat[NB * NC * HW];
__device__ float g_pp[NBC * 4 * 25];
__device__ float g_filt[NBC * 25];

__device__ __forceinline__ u64 fma2(u64 a, u64 b, u64 c) {
    u64 d;
    asm("fma.rn.f32x2 %0, %1, %2, %3;" : "=l"(d) : "l"(a), "l"(b), "l"(c));
    return d;
}
__device__ __forceinline__ u64 dup(float f) {
    unsigned u = __float_as_uint(f);
    return ((u64)u << 32) | (u64)u;
}
__device__ __forceinline__ u64 pack(unsigned lo, unsigned hi) {
    u64 d;
    asm("mov.b64 %0, {%1, %2};" : "=l"(d) : "r"(lo), "r"(hi));
    return d;
}

// ---------------------------------------------------------------------------
// Kernel 1: channel mix. Block = 2 image rows (512 px) x all 32 channels.
// Stage x tile in SMEM (coalesced LDG.128), then each thread owns one
// float2 pixel pair with 32 packed accumulators: every staged x value is
// read from SMEM exactly once per thread (no re-read blowup).
// grid = (128, 8), block = 256, dyn smem = 74 KB -> 2 blocks/SM
// ---------------------------------------------------------------------------
__global__ __launch_bounds__(256, 2) void mix_kernel(
    const float* __restrict__ x,
    const float* __restrict__ w,
    const float* __restrict__ bias)
{
    extern __shared__ u64 sm[];
    u64* xs2 = sm;             // [32][256] pixel pairs
    u64* w2  = sm + 32 * 256;  // [32][32] duplicated weights
    u64* b2  = w2 + 1024;      // [32]

    int tid = threadIdx.x;
    for (int idx = tid; idx < 1024; idx += 256)
        w2[idx] = dup(w[idx]);
    if (tid < 32)
        b2[tid] = dup(bias[tid]);

    int b = blockIdx.y;
    const float4* xb = (const float4*)(x + (size_t)b * (NC * HW) + blockIdx.x * 512);
#pragma unroll
    for (int k = 0; k < 16; k++) {
        int e = tid + k * 256;          // 0..4095
        int i = e >> 7;                 // channel
        int c = e & 127;                // float4 within the 512-px row pair
        float4 v = xb[(size_t)i * (HW / 4) + c];
        xs2[i * 256 + c * 2]     = pack(__float_as_uint(v.x), __float_as_uint(v.y));
        xs2[i * 256 + c * 2 + 1] = pack(__float_as_uint(v.z), __float_as_uint(v.w));
    }
    __syncthreads();

    u64 acc[32];
#pragma unroll
    for (int o = 0; o < 32; o++) acc[o] = b2[o];

#pragma unroll
    for (int i = 0; i < 32; i++) {
        u64 xv = xs2[i * 256 + tid];
#pragma unroll
        for (int o = 0; o < 32; o++)
            acc[o] = fma2(w2[o * 32 + i], xv, acc[o]);
    }

    u64* fb = (u64*)g_feat + (size_t)b * (NC * (HW / 2)) + blockIdx.x * 256 + tid;
#pragma unroll
    for (int o = 0; o < 32; o++)
        fb[(size_t)o * (HW / 2)] = acc[o];
}

// ---------------------------------------------------------------------------
// Kernel 2: adaptive pool partials on x. Block = (b*32+i, row-chunk q of 64
// rows). Row bins [0,52)[51,103)[102,154)[153,205)[204,256) (overlapping).
// grid = (256, 4), block = 256 (thread = column)
// ---------------------------------------------------------------------------
__global__ __launch_bounds__(256) void pool_kernel(const float* __restrict__ x)
{
    __shared__ float pool[25];
    int bc = blockIdx.x;
    int q  = blockIdx.y;
    int w  = threadIdx.x;
    if (w < 25) pool[w] = 0.0f;
    __syncthreads();

    const float* img = x + (size_t)bc * HW + (size_t)q * 64 * 256;

    float cs[5] = {0.f, 0.f, 0.f, 0.f, 0.f};
#pragma unroll
    for (int r = 0; r < 64; r++) {
        int h = q * 64 + r;
        float v = img[r * 256 + w];
        if (h < 52)              cs[0] += v;
        if (h >= 51 && h < 103)  cs[1] += v;
        if (h >= 102 && h < 154) cs[2] += v;
        if (h >= 153 && h < 205) cs[3] += v;
        if (h >= 204)            cs[4] += v;
    }

#pragma unroll
    for (int l = 0; l < 5; l++) {
        int s = (l * 256) / 5;
        int e = ((l + 1) * 256 + 4) / 5;
        if (w >= s && w < e) {
#pragma unroll
            for (int k = 0; k < 5; k++)
                if (cs[k] != 0.0f)             // adding 0 is a no-op; skip
                    atomicAdd(&pool[k * 5 + l], cs[k]);
        }
    }
    __syncthreads();
    if (w < 25)
        g_pp[(bc * 4 + q) * 25 + w] = pool[w];
}

// ---------------------------------------------------------------------------
// Kernel 3: filt[b,o,kl] = bias[o] + sum_i w[o,i] * px[b,i,kl]
// (pooling commutes with the 1x1 conv: pool matrix is row-stochastic)
// grid = 8, block = 800
// ---------------------------------------------------------------------------
__global__ void filt_kernel(const float* __restrict__ w,
                            const float* __restrict__ bias)
{
    __shared__ float spx[800];
    int b = blockIdx.x;
    int t = threadIdx.x;
    int i  = t / 25;
    int kl = t - i * 25;

    float s = 0.0f;
#pragma unroll
    for (int q = 0; q < 4; q++)
        s += g_pp[((b * 32 + i) * 4 + q) * 25 + kl];
    spx[t] = s * (1.0f / 2704.0f);       // 52*52 bin area
    __syncthreads();

    float acc = bias[i];                 // here i plays the role of o
#pragma unroll
    for (int ic = 0; ic < 32; ic++)
        acc += w[i * 32 + ic] * spx[ic * 25 + kl];
    g_filt[b * 800 + t] = acc;
}

// ---------------------------------------------------------------------------
// Kernel 4: depthwise 5x5 'same' conv, packed f32x2. Tile 64x64 outputs;
// thread computes a 2-wide x 8-high patch. Even-offset input pairs come
// directly from LDS.64; odd-offset pairs via one mov.b64 from halves.
// grid = (16, 256), block = 256, smem = 18.5 KB
// ---------------------------------------------------------------------------
__global__ __launch_bounds__(256, 2) void conv_kernel(float* __restrict__ out)
{
    __shared__ float sh[68 * 68];

    int bc  = blockIdx.y;
    int tx0 = (blockIdx.x & 3) * 64;
    int ty0 = (blockIdx.x >> 2) * 64;

    const float* img = g_feat + (size_t)bc * HW;

    u64 f2r[25];
#pragma unroll
    for (int t = 0; t < 25; t++) f2r[t] = dup(g_filt[bc * 25 + t]);

    for (int idx = threadIdx.x; idx < 68 * 68; idx += 256) {
        int r = idx / 68;
        int c = idx - r * 68;
        int gy = ty0 + r - 2;
        int gx = tx0 + c - 2;
        float v = 0.0f;
        if ((unsigned)gy < 256u && (unsigned)gx < 256u)
            v = img[gy * 256 + gx];
        sh[idx] = v;
    }
    __syncthreads();

    int x  = (threadIdx.x & 31) * 2;      // output col pair
    int oy = (threadIdx.x >> 5) * 8;      // first output row

    u64 acc[8];
#pragma unroll
    for (int j = 0; j < 8; j++) acc[j] = 0ull;

#pragma unroll
    for (int r = 0; r < 12; r++) {
        const float* row = sh + (oy + r) * 68 + x;
        u64 q0 = *(const u64*)(row);       // (v0,v1)
        u64 q2 = *(const u64*)(row + 2);   // (v2,v3)
        u64 q4 = *(const u64*)(row + 4);   // (v4,v5)
        u64 p1 = pack((unsigned)(q0 >> 32), (unsigned)q2);          // (v1,v2)
        u64 p3 = pack((unsigned)(q2 >> 32), (unsigned)q4);          // (v3,v4)
#pragma unroll
        for (int ky = 0; ky < 5; ky++) {
            int j = r - ky;
            if (j >= 0 && j < 8) {
                acc[j] = fma2(f2r[ky * 5 + 0], q0, acc[j]);
                acc[j] = fma2(f2r[ky * 5 + 1], p1, acc[j]);
                acc[j] = fma2(f2r[ky * 5 + 2], q2, acc[j]);
                acc[j] = fma2(f2r[ky * 5 + 3], p3, acc[j]);
                acc[j] = fma2(f2r[ky * 5 + 4], q4, acc[j]);
            }
        }
    }

    float* op = out + (size_t)bc * HW + (size_t)(ty0 + oy) * 256 + tx0 + x;
#pragma unroll
    for (int j = 0; j < 8; j++)
        *(u64*)(op + (size_t)j * 256) = acc[j];
}

// ---------------------------------------------------------------------------
extern "C" void kernel_launch(void* const* d_in, const int* in_sizes, int n_in,
                              void* d_out, int out_size)
{
    const float* x    = (const float*)d_in[0];   // [8, 32, 256, 256]
    const float* w    = (const float*)d_in[1];   // [32, 32]
    const float* bias = (const float*)d_in[2];   // [32]
    float* out = (float*)d_out;                  // [8, 32, 256, 256]

    const int mix_smem = (32 * 256 + 1024 + 32) * 8;   // 73984 B
    cudaFuncSetAttribute(mix_kernel,
                         cudaFuncAttributeMaxDynamicSharedMemorySize, mix_smem);

    mix_kernel<<<dim3(128, NB), 256, mix_smem>>>(x, w, bias);
    pool_kernel<<<dim3(NBC, 4), 256>>>(x);
    filt_kernel<<<NB, 800>>>(w, bias);
    conv_kernel<<<dim3(16, NBC), 256>>>(out);
}